// round 3
// baseline (speedup 1.0000x reference)
#include <cuda_runtime.h>
#include <cuda_bf16.h>
#include <stdint.h>

// Problem constants
static constexpr int Bn = 4, Gn = 6, Hn = 8, Sn = 1024, DKn = 64, DMn = 512;
static constexpr int BG   = Bn * Gn;        // 24
static constexpr int BGH  = BG * Hn;        // 192
static constexpr int MROWS = BG * Sn;       // 24576
static constexpr int P_ELEMS = 201326592;   // 192*1024*1024
static constexpr int Y_ELEMS = BG * DMn;    // 12288

// Scratch (__device__ globals: allocation-free)
__device__ __align__(16) __nv_bfloat16 g_q[(size_t)MROWS * DMn];
__device__ __align__(16) __nv_bfloat16 g_k[(size_t)MROWS * DMn];
__device__ __align__(16) float g_wbar[BGH * Sn];
__device__ __align__(16) float g_t[BG * Hn * DMn];   // 24*8*512 partial t accum

__device__ __forceinline__ void mma16816(float c[4], const uint32_t a[4], const uint32_t b[2]) {
    asm volatile(
        "mma.sync.aligned.m16n8k16.row.col.f32.bf16.bf16.f32 "
        "{%0,%1,%2,%3},{%4,%5,%6,%7},{%8,%9},{%0,%1,%2,%3};\n"
        : "+f"(c[0]), "+f"(c[1]), "+f"(c[2]), "+f"(c[3])
        : "r"(a[0]), "r"(a[1]), "r"(a[2]), "r"(a[3]), "r"(b[0]), "r"(b[1]));
}

// ---------------------------------------------------------------------------
// Zero wbar (192*1024 floats) and g_t (24*4096 floats). grid 288 x 256thr x 4f
__global__ void zero_kernel() {
    int i = blockIdx.x * 1024 + threadIdx.x * 4;
    float4 z = make_float4(0.f, 0.f, 0.f, 0.f);
    if (i < BGH * Sn) *(float4*)&g_wbar[i] = z;
    else              *(float4*)&g_t[i - BGH * Sn] = z;
}

// ---------------------------------------------------------------------------
// Projection: y = x @ W^T + b, output bf16 in (bg, h, s, d) layout.
// Grid: (192 m-tiles, 4 n-tiles, 2 {q,k}), 256 threads.
__global__ __launch_bounds__(256) void proj_kernel(
    const float* __restrict__ xq, const float* __restrict__ xk,
    const float* __restrict__ Wq, const float* __restrict__ bq,
    const float* __restrict__ Wk, const float* __restrict__ bk)
{
    const int which = blockIdx.z;
    const float* __restrict__ X  = which ? xk : xq;
    const float* __restrict__ W  = which ? Wk : Wq;
    const float* __restrict__ Bi = which ? bk : bq;
    __nv_bfloat16* O = which ? g_k : g_q;

    const int m0 = blockIdx.x * 128;
    const int n0 = blockIdx.y * 128;
    const int tid = threadIdx.x;
    const int w = tid >> 5, lane = tid & 31;
    const int gq = lane >> 2, tq = lane & 3;
    const int wm = w >> 1, wn = w & 1;   // 4x2 warp grid -> warp tile 32(m) x 64(n)

    __shared__ __nv_bfloat16 As[128 * 40];
    __shared__ __nv_bfloat16 Bs[128 * 40];

    float acc[2][8][4];
#pragma unroll
    for (int mi = 0; mi < 2; mi++)
#pragma unroll
        for (int ni = 0; ni < 8; ni++)
#pragma unroll
            for (int x = 0; x < 4; x++) acc[mi][ni][x] = 0.f;

    float4 ra[4], rb[4];
#pragma unroll
    for (int j = 0; j < 4; j++) {
        int i = tid + 256 * j;
        int r = i >> 3, c4 = (i & 7) * 4;
        ra[j] = *(const float4*)&X[(size_t)(m0 + r) * DMn + c4];
        rb[j] = *(const float4*)&W[(size_t)(n0 + r) * DMn + c4];
    }

    for (int kc = 0; kc < 16; kc++) {
        __syncthreads();
#pragma unroll
        for (int j = 0; j < 4; j++) {
            int i = tid + 256 * j;
            int r = i >> 3, c4 = (i & 7) * 4;
            __nv_bfloat162 lo = __floats2bfloat162_rn(ra[j].x, ra[j].y);
            __nv_bfloat162 hi = __floats2bfloat162_rn(ra[j].z, ra[j].w);
            *(__nv_bfloat162*)&As[r * 40 + c4]     = lo;
            *(__nv_bfloat162*)&As[r * 40 + c4 + 2] = hi;
            lo = __floats2bfloat162_rn(rb[j].x, rb[j].y);
            hi = __floats2bfloat162_rn(rb[j].z, rb[j].w);
            *(__nv_bfloat162*)&Bs[r * 40 + c4]     = lo;
            *(__nv_bfloat162*)&Bs[r * 40 + c4 + 2] = hi;
        }
        __syncthreads();
        if (kc < 15) {
            int kk = (kc + 1) * 32;
#pragma unroll
            for (int j = 0; j < 4; j++) {
                int i = tid + 256 * j;
                int r = i >> 3, c4 = (i & 7) * 4;
                ra[j] = *(const float4*)&X[(size_t)(m0 + r) * DMn + kk + c4];
                rb[j] = *(const float4*)&W[(size_t)(n0 + r) * DMn + kk + c4];
            }
        }
#pragma unroll
        for (int ks = 0; ks < 32; ks += 16) {
            uint32_t af[2][4];
#pragma unroll
            for (int mi = 0; mi < 2; mi++) {
                int ar = wm * 32 + mi * 16;
                af[mi][0] = *(const uint32_t*)&As[(ar + gq) * 40 + ks + 2 * tq];
                af[mi][1] = *(const uint32_t*)&As[(ar + gq + 8) * 40 + ks + 2 * tq];
                af[mi][2] = *(const uint32_t*)&As[(ar + gq) * 40 + ks + 2 * tq + 8];
                af[mi][3] = *(const uint32_t*)&As[(ar + gq + 8) * 40 + ks + 2 * tq + 8];
            }
#pragma unroll
            for (int ni = 0; ni < 8; ni++) {
                int br = wn * 64 + ni * 8 + gq;
                uint32_t bf[2];
                bf[0] = *(const uint32_t*)&Bs[br * 40 + ks + 2 * tq];
                bf[1] = *(const uint32_t*)&Bs[br * 40 + ks + 2 * tq + 8];
#pragma unroll
                for (int mi = 0; mi < 2; mi++) mma16816(acc[mi][ni], af[mi], bf);
            }
        }
    }

    // Epilogue: +bias, convert bf16, write to (bg,h,s,d) layout
#pragma unroll
    for (int ni = 0; ni < 8; ni++) {
        int cc = n0 + wn * 64 + ni * 8 + 2 * tq;
        float b0v = Bi[cc], b1v = Bi[cc + 1];
        int h = cc >> 6, d = cc & 63;
#pragma unroll
        for (int mi = 0; mi < 2; mi++) {
            int rbase = m0 + wm * 32 + mi * 16 + gq;
#pragma unroll
            for (int rr = 0; rr < 2; rr++) {
                int r = rbase + rr * 8;
                int bg = r >> 10, s = r & 1023;
                size_t off = ((size_t)(bg * Hn + h) * Sn + s) * DKn + d;
                float v0 = acc[mi][ni][rr * 2 + 0] + b0v;
                float v1 = acc[mi][ni][rr * 2 + 1] + b1v;
                *(__nv_bfloat162*)&O[off] = __floats2bfloat162_rn(v0, v1);
            }
        }
    }
}

// ---------------------------------------------------------------------------
// Attention v2: two-pass recompute. Per CTA = 32 q-rows x 1024 k of one bgh.
// Pass A: MMA + exp -> rowsums only (registers). Pass B: recompute MMA
// (deterministic, identical values), scale by 1/rowsum, stage 32x128 chunk in
// smem, coalesced float4 writes + column sums.
static constexpr int KSTR = 72;    // bf16 row stride of k/q tiles
static constexpr int CSTR = 132;   // fp32 row stride of staging chunk
static constexpr int SM_QS   = 0;                          // 32*72*2   = 4608
static constexpr int SM_KS   = SM_QS + 32 * KSTR * 2;      // 2*128*72*2= 36864
static constexpr int SM_ES   = SM_KS + 2 * 128 * KSTR * 2; // 32*132*4  = 16896
static constexpr int SM_RSUM = SM_ES + 32 * CSTR * 4;      // 32*4
static constexpr int SM_CSUM = SM_RSUM + 32 * 4;           // 1024*4
static constexpr int ATTN_SMEM = SM_CSUM + 1024 * 4;       // 62624 B

__global__ __launch_bounds__(256) void attn_kernel(float* __restrict__ out, int p_base, int write_p)
{
    extern __shared__ char smbuf[];
    __nv_bfloat16* qs   = (__nv_bfloat16*)(smbuf + SM_QS);
    __nv_bfloat16* ksm  = (__nv_bfloat16*)(smbuf + SM_KS);
    float*         es   = (float*)(smbuf + SM_ES);
    float*         rsum = (float*)(smbuf + SM_RSUM);
    float*         csum = (float*)(smbuf + SM_CSUM);

    const int qt = blockIdx.x, bgh = blockIdx.y;
    const int tid = threadIdx.x;
    const int w = tid >> 5, lane = tid & 31;
    const int gq = lane >> 2, tq = lane & 3;
    const int wm = w & 1, wn = w >> 1;   // 2(m) x 4(n) warps over 32 x 128

    const __nv_bfloat16* qbase = g_q + (size_t)bgh * (Sn * DKn) + (size_t)qt * 32 * DKn;
    const __nv_bfloat16* kbase = g_k + (size_t)bgh * (Sn * DKn);

    // q tile (32x64 bf16), rsum/csum init
    {
        int r = tid >> 3, part = tid & 7;
        *(uint4*)&qs[r * KSTR + part * 8] = *(const uint4*)&qbase[r * DKn + part * 8];
    }
    if (tid < 32) rsum[tid] = 0.f;
    *(float4*)&csum[tid * 4] = make_float4(0.f, 0.f, 0.f, 0.f);

    const float SCL = 1.0f / 1200.0f;  // 1/(sqrt(64)*150)
    const int ldr = tid >> 3, ldp = (tid & 7) * 8;   // k-chunk loader coords

    // ---------------- Pass A: rowsums ----------------
    uint4 pre[4];
#pragma unroll
    for (int j = 0; j < 4; j++)
        pre[j] = *(const uint4*)&kbase[(size_t)(ldr + 32 * j) * DKn + ldp];

    float rs0 = 0.f, rs1 = 0.f;
    for (int c = 0; c < 8; c++) {
        __nv_bfloat16* kbuf = ksm + (c & 1) * 128 * KSTR;
#pragma unroll
        for (int j = 0; j < 4; j++)
            *(uint4*)&kbuf[(ldr + 32 * j) * KSTR + ldp] = pre[j];
        __syncthreads();
        if (c < 7) {
#pragma unroll
            for (int j = 0; j < 4; j++)
                pre[j] = *(const uint4*)&kbase[(size_t)((c + 1) * 128 + ldr + 32 * j) * DKn + ldp];
        }

        float acc[4][4];
#pragma unroll
        for (int ni = 0; ni < 4; ni++)
#pragma unroll
            for (int x = 0; x < 4; x++) acc[ni][x] = 0.f;

#pragma unroll
        for (int ks = 0; ks < 64; ks += 16) {
            uint32_t af[4];
            int ar = wm * 16;
            af[0] = *(const uint32_t*)&qs[(ar + gq) * KSTR + ks + 2 * tq];
            af[1] = *(const uint32_t*)&qs[(ar + gq + 8) * KSTR + ks + 2 * tq];
            af[2] = *(const uint32_t*)&qs[(ar + gq) * KSTR + ks + 2 * tq + 8];
            af[3] = *(const uint32_t*)&qs[(ar + gq + 8) * KSTR + ks + 2 * tq + 8];
#pragma unroll
            for (int ni = 0; ni < 4; ni++) {
                int br = wn * 32 + ni * 8 + gq;
                uint32_t bf[2];
                bf[0] = *(const uint32_t*)&kbuf[br * KSTR + ks + 2 * tq];
                bf[1] = *(const uint32_t*)&kbuf[br * KSTR + ks + 2 * tq + 8];
                mma16816(acc[ni], af, bf);
            }
        }
#pragma unroll
        for (int ni = 0; ni < 4; ni++) {
            rs0 += __expf(acc[ni][0] * SCL) + __expf(acc[ni][1] * SCL);
            rs1 += __expf(acc[ni][2] * SCL) + __expf(acc[ni][3] * SCL);
        }
        __syncthreads();
    }

    rs0 += __shfl_xor_sync(0xffffffffu, rs0, 1);
    rs0 += __shfl_xor_sync(0xffffffffu, rs0, 2);
    rs1 += __shfl_xor_sync(0xffffffffu, rs1, 1);
    rs1 += __shfl_xor_sync(0xffffffffu, rs1, 2);
    if (tq == 0) {
        atomicAdd(&rsum[wm * 16 + gq], rs0);
        atomicAdd(&rsum[wm * 16 + 8 + gq], rs1);
    }
    __syncthreads();
    if (tid < 32) rsum[tid] = 1.0f / rsum[tid];

    // ---------------- Pass B: recompute, normalize, write ----------------
#pragma unroll
    for (int j = 0; j < 4; j++)
        pre[j] = *(const uint4*)&kbase[(size_t)(ldr + 32 * j) * DKn + ldp];
    __syncthreads();   // rsum inverted + pass A fully done

    float* pout = out + p_base + (size_t)bgh * ((size_t)Sn * Sn) + (size_t)(qt * 32) * Sn;
    const int wr_r = tid >> 5;          // writer: rows wr_r, wr_r+8, +16, +24
    const int wr_c = (tid & 31) * 4;    // 4 cols within chunk

    for (int c = 0; c < 8; c++) {
        __nv_bfloat16* kbuf = ksm + (c & 1) * 128 * KSTR;
#pragma unroll
        for (int j = 0; j < 4; j++)
            *(uint4*)&kbuf[(ldr + 32 * j) * KSTR + ldp] = pre[j];
        __syncthreads();
        if (c < 7) {
#pragma unroll
            for (int j = 0; j < 4; j++)
                pre[j] = *(const uint4*)&kbase[(size_t)((c + 1) * 128 + ldr + 32 * j) * DKn + ldp];
        }

        float acc[4][4];
#pragma unroll
        for (int ni = 0; ni < 4; ni++)
#pragma unroll
            for (int x = 0; x < 4; x++) acc[ni][x] = 0.f;

#pragma unroll
        for (int ks = 0; ks < 64; ks += 16) {
            uint32_t af[4];
            int ar = wm * 16;
            af[0] = *(const uint32_t*)&qs[(ar + gq) * KSTR + ks + 2 * tq];
            af[1] = *(const uint32_t*)&qs[(ar + gq + 8) * KSTR + ks + 2 * tq];
            af[2] = *(const uint32_t*)&qs[(ar + gq) * KSTR + ks + 2 * tq + 8];
            af[3] = *(const uint32_t*)&qs[(ar + gq + 8) * KSTR + ks + 2 * tq + 8];
#pragma unroll
            for (int ni = 0; ni < 4; ni++) {
                int br = wn * 32 + ni * 8 + gq;
                uint32_t bf[2];
                bf[0] = *(const uint32_t*)&kbuf[br * KSTR + ks + 2 * tq];
                bf[1] = *(const uint32_t*)&kbuf[br * KSTR + ks + 2 * tq + 8];
                mma16816(acc[ni], af, bf);
            }
        }

        // stage exp values (unnormalized) into chunk tile
        int r0 = wm * 16 + gq;
#pragma unroll
        for (int ni = 0; ni < 4; ni++) {
            int cc = wn * 32 + ni * 8 + 2 * tq;
            *(float2*)&es[r0 * CSTR + cc] =
                make_float2(__expf(acc[ni][0] * SCL), __expf(acc[ni][1] * SCL));
            *(float2*)&es[(r0 + 8) * CSTR + cc] =
                make_float2(__expf(acc[ni][2] * SCL), __expf(acc[ni][3] * SCL));
        }
        __syncthreads();

        // writer: normalize, coalesced float4 store, column sums
        float cs0 = 0.f, cs1 = 0.f, cs2 = 0.f, cs3 = 0.f;
#pragma unroll
        for (int j = 0; j < 4; j++) {
            int r = wr_r + j * 8;
            float inv = rsum[r];
            float4 v = *(const float4*)&es[r * CSTR + wr_c];
            v.x *= inv; v.y *= inv; v.z *= inv; v.w *= inv;
            cs0 += v.x; cs1 += v.y; cs2 += v.z; cs3 += v.w;
            if (write_p) *(float4*)&pout[(size_t)r * Sn + c * 128 + wr_c] = v;
        }
        int cb = c * 128 + wr_c;
        atomicAdd(&csum[cb + 0], cs0);
        atomicAdd(&csum[cb + 1], cs1);
        atomicAdd(&csum[cb + 2], cs2);
        atomicAdd(&csum[cb + 3], cs3);
        __syncthreads();
    }

    // flush column sums (one atomic per column per CTA)
    float4 cv = *(const float4*)&csum[tid * 4];
    atomicAdd(&g_wbar[bgh * Sn + tid * 4 + 0], cv.x);
    atomicAdd(&g_wbar[bgh * Sn + tid * 4 + 1], cv.y);
    atomicAdd(&g_wbar[bgh * Sn + tid * 4 + 2], cv.z);
    atomicAdd(&g_wbar[bgh * Sn + tid * 4 + 3], cv.w);
}

// ---------------------------------------------------------------------------
// t = (wbar/1024) @ Xv, parallelized over (bg, 16 S-chunks of 64).
__global__ __launch_bounds__(256) void t_kernel(const float* __restrict__ value)
{
    __shared__ float wb[8][64];
    const int bg = blockIdx.x, kc = blockIdx.y;
    const int tid = threadIdx.x;

    for (int j = tid; j < 512; j += 256) {
        int h = j >> 6, k = j & 63;
        wb[h][k] = g_wbar[(bg * 8 + h) * Sn + kc * 64 + k] * (1.0f / 1024.0f);
    }
    __syncthreads();

    float a[8][2];
#pragma unroll
    for (int h = 0; h < 8; h++) { a[h][0] = 0.f; a[h][1] = 0.f; }

    const float* __restrict__ xv = value + (size_t)bg * (Sn * DMn) + (size_t)(kc * 64) * DMn;
#pragma unroll 4
    for (int k = 0; k < 64; k++) {
        float x0 = xv[k * DMn + tid];
        float x1 = xv[k * DMn + tid + 256];
#pragma unroll
        for (int h = 0; h < 8; h++) {
            a[h][0] += wb[h][k] * x0;
            a[h][1] += wb[h][k] * x1;
        }
    }
#pragma unroll
    for (int h = 0; h < 8; h++) {
        atomicAdd(&g_t[(bg * 8 + h) * DMn + tid],       a[h][0]);
        atomicAdd(&g_t[(bg * 8 + h) * DMn + tid + 256], a[h][1]);
    }
}

// ---------------------------------------------------------------------------
// finalize2: out_hd = t_h . Wv[h*64+d] + bv ; f[d*8+h] = out_hd ;
// y = f @ Wo^T + bo.  One CTA per (b,g), 512 threads, row-contiguous W loads.
__global__ __launch_bounds__(512) void finalize2_kernel(
    const float* __restrict__ Wv, const float* __restrict__ bv,
    const float* __restrict__ Wo, const float* __restrict__ bo,
    float* __restrict__ out, int write_y)
{
    __shared__ float ts[8 * 512];
    __shared__ float fs[512];
    const int bg = blockIdx.x, tid = threadIdx.x;

#pragma unroll
    for (int j = 0; j < 8; j++) ts[j * 512 + tid] = g_t[bg * 4096 + j * 512 + tid];
    __syncthreads();

    {
        int h = tid >> 6, d = tid & 63;
        const float4* __restrict__ wr = (const float4*)(Wv + (size_t)tid * DMn);
        const float* th = ts + h * 512;
        float o0 = 0, o1 = 0, o2 = 0, o3 = 0;
#pragma unroll 8
        for (int c = 0; c < 128; c++) {
            float4 w4 = wr[c];
            o0 += th[4 * c + 0] * w4.x;
            o1 += th[4 * c + 1] * w4.y;
            o2 += th[4 * c + 2] * w4.z;
            o3 += th[4 * c + 3] * w4.w;
        }
        fs[d * 8 + h] = bv[tid] + ((o0 + o1) + (o2 + o3));
    }
    __syncthreads();

    if (write_y) {
        const float4* __restrict__ wr = (const float4*)(Wo + (size_t)tid * DMn);
        float o0 = 0, o1 = 0, o2 = 0, o3 = 0;
#pragma unroll 8
        for (int c = 0; c < 128; c++) {
            float4 w4 = wr[c];
            o0 += fs[4 * c + 0] * w4.x;
            o1 += fs[4 * c + 1] * w4.y;
            o2 += fs[4 * c + 2] * w4.z;
            o3 += fs[4 * c + 3] * w4.w;
        }
        out[bg * DMn + tid] = bo[tid] + ((o0 + o1) + (o2 + o3));
    }
}

// ---------------------------------------------------------------------------
extern "C" void kernel_launch(void* const* d_in, const int* in_sizes, int n_in,
                              void* d_out, int out_size)
{
    if (n_in < 11) return;
    const float* query = (const float*)d_in[0];
    const float* key   = (const float*)d_in[1];
    const float* value = (const float*)d_in[2];
    const float* Wq = (const float*)d_in[3];
    const float* bq = (const float*)d_in[4];
    const float* Wk = (const float*)d_in[5];
    const float* bk = (const float*)d_in[6];
    const float* Wv = (const float*)d_in[7];
    const float* bv = (const float*)d_in[8];
    const float* Wo = (const float*)d_in[9];
    const float* bo = (const float*)d_in[10];
    float* out = (float*)d_out;

    const int write_p = (out_size >= P_ELEMS) ? 1 : 0;
    const int p_base  = (out_size > P_ELEMS) ? Y_ELEMS : 0;
    const int write_y = (out_size == Y_ELEMS || out_size == Y_ELEMS + P_ELEMS) ? 1 : 0;

    cudaFuncSetAttribute((const void*)attn_kernel,
                         cudaFuncAttributeMaxDynamicSharedMemorySize, ATTN_SMEM);

    zero_kernel<<<288, 256>>>();
    proj_kernel<<<dim3(192, 4, 2), 256>>>(query, key, Wq, bq, Wk, bk);
    attn_kernel<<<dim3(32, 192), 256, ATTN_SMEM>>>(out, p_base, write_p);
    t_kernel<<<dim3(BG, 16), 256>>>(value);
    finalize2_kernel<<<BG, 512>>>(Wv, bv, Wo, bo, out, write_y);
}

// round 4
// speedup vs baseline: 1.1403x; 1.1403x over previous
#include <cuda_runtime.h>
#include <cuda_bf16.h>
#include <stdint.h>

// Problem constants
static constexpr int Bn = 4, Gn = 6, Hn = 8, Sn = 1024, DKn = 64, DMn = 512;
static constexpr int BG   = Bn * Gn;        // 24
static constexpr int BGH  = BG * Hn;        // 192
static constexpr int MROWS = BG * Sn;       // 24576
static constexpr int P_ELEMS = 201326592;   // 192*1024*1024
static constexpr int Y_ELEMS = BG * DMn;    // 12288

// Scratch (__device__ globals: allocation-free)
__device__ __align__(16) __nv_bfloat16 g_q[(size_t)MROWS * DMn];
__device__ __align__(16) __nv_bfloat16 g_k[(size_t)MROWS * DMn];
__device__ __align__(16) float g_wbar[BGH * Sn];
__device__ __align__(16) float g_t[BG * Hn * DMn];   // 24*8*512 partial t accum

__device__ __forceinline__ void mma16816(float c[4], const uint32_t a[4], const uint32_t b[2]) {
    asm volatile(
        "mma.sync.aligned.m16n8k16.row.col.f32.bf16.bf16.f32 "
        "{%0,%1,%2,%3},{%4,%5,%6,%7},{%8,%9},{%0,%1,%2,%3};\n"
        : "+f"(c[0]), "+f"(c[1]), "+f"(c[2]), "+f"(c[3])
        : "r"(a[0]), "r"(a[1]), "r"(a[2]), "r"(a[3]), "r"(b[0]), "r"(b[1]));
}

// ---------------------------------------------------------------------------
// Zero wbar (192*1024 floats) and g_t (24*4096 floats). grid 288 x 256thr x 4f
__global__ void zero_kernel() {
    int i = blockIdx.x * 1024 + threadIdx.x * 4;
    float4 z = make_float4(0.f, 0.f, 0.f, 0.f);
    if (i < BGH * Sn) *(float4*)&g_wbar[i] = z;
    else              *(float4*)&g_t[i - BGH * Sn] = z;
}

// ---------------------------------------------------------------------------
// Projection: y = x @ W^T + b, output bf16 in (bg, h, s, d) layout.
// Grid: (192 m-tiles, 4 n-tiles, 2 {q,k}), 256 threads.
__global__ __launch_bounds__(256) void proj_kernel(
    const float* __restrict__ xq, const float* __restrict__ xk,
    const float* __restrict__ Wq, const float* __restrict__ bq,
    const float* __restrict__ Wk, const float* __restrict__ bk)
{
    const int which = blockIdx.z;
    const float* __restrict__ X  = which ? xk : xq;
    const float* __restrict__ W  = which ? Wk : Wq;
    const float* __restrict__ Bi = which ? bk : bq;
    __nv_bfloat16* O = which ? g_k : g_q;

    const int m0 = blockIdx.x * 128;
    const int n0 = blockIdx.y * 128;
    const int tid = threadIdx.x;
    const int w = tid >> 5, lane = tid & 31;
    const int gq = lane >> 2, tq = lane & 3;
    const int wm = w >> 1, wn = w & 1;   // 4x2 warp grid -> warp tile 32(m) x 64(n)

    __shared__ __nv_bfloat16 As[128 * 40];
    __shared__ __nv_bfloat16 Bs[128 * 40];

    float acc[2][8][4];
#pragma unroll
    for (int mi = 0; mi < 2; mi++)
#pragma unroll
        for (int ni = 0; ni < 8; ni++)
#pragma unroll
            for (int x = 0; x < 4; x++) acc[mi][ni][x] = 0.f;

    float4 ra[4], rb[4];
#pragma unroll
    for (int j = 0; j < 4; j++) {
        int i = tid + 256 * j;
        int r = i >> 3, c4 = (i & 7) * 4;
        ra[j] = *(const float4*)&X[(size_t)(m0 + r) * DMn + c4];
        rb[j] = *(const float4*)&W[(size_t)(n0 + r) * DMn + c4];
    }

    for (int kc = 0; kc < 16; kc++) {
        __syncthreads();
#pragma unroll
        for (int j = 0; j < 4; j++) {
            int i = tid + 256 * j;
            int r = i >> 3, c4 = (i & 7) * 4;
            __nv_bfloat162 lo = __floats2bfloat162_rn(ra[j].x, ra[j].y);
            __nv_bfloat162 hi = __floats2bfloat162_rn(ra[j].z, ra[j].w);
            *(__nv_bfloat162*)&As[r * 40 + c4]     = lo;
            *(__nv_bfloat162*)&As[r * 40 + c4 + 2] = hi;
            lo = __floats2bfloat162_rn(rb[j].x, rb[j].y);
            hi = __floats2bfloat162_rn(rb[j].z, rb[j].w);
            *(__nv_bfloat162*)&Bs[r * 40 + c4]     = lo;
            *(__nv_bfloat162*)&Bs[r * 40 + c4 + 2] = hi;
        }
        __syncthreads();
        if (kc < 15) {
            int kk = (kc + 1) * 32;
#pragma unroll
            for (int j = 0; j < 4; j++) {
                int i = tid + 256 * j;
                int r = i >> 3, c4 = (i & 7) * 4;
                ra[j] = *(const float4*)&X[(size_t)(m0 + r) * DMn + kk + c4];
                rb[j] = *(const float4*)&W[(size_t)(n0 + r) * DMn + kk + c4];
            }
        }
#pragma unroll
        for (int ks = 0; ks < 32; ks += 16) {
            uint32_t af[2][4];
#pragma unroll
            for (int mi = 0; mi < 2; mi++) {
                int ar = wm * 32 + mi * 16;
                af[mi][0] = *(const uint32_t*)&As[(ar + gq) * 40 + ks + 2 * tq];
                af[mi][1] = *(const uint32_t*)&As[(ar + gq + 8) * 40 + ks + 2 * tq];
                af[mi][2] = *(const uint32_t*)&As[(ar + gq) * 40 + ks + 2 * tq + 8];
                af[mi][3] = *(const uint32_t*)&As[(ar + gq + 8) * 40 + ks + 2 * tq + 8];
            }
#pragma unroll
            for (int ni = 0; ni < 8; ni++) {
                int br = wn * 64 + ni * 8 + gq;
                uint32_t bf[2];
                bf[0] = *(const uint32_t*)&Bs[br * 40 + ks + 2 * tq];
                bf[1] = *(const uint32_t*)&Bs[br * 40 + ks + 2 * tq + 8];
#pragma unroll
                for (int mi = 0; mi < 2; mi++) mma16816(acc[mi][ni], af[mi], bf);
            }
        }
    }

    // Epilogue: +bias, convert bf16, write to (bg,h,s,d) layout
#pragma unroll
    for (int ni = 0; ni < 8; ni++) {
        int cc = n0 + wn * 64 + ni * 8 + 2 * tq;
        float b0v = Bi[cc], b1v = Bi[cc + 1];
        int h = cc >> 6, d = cc & 63;
#pragma unroll
        for (int mi = 0; mi < 2; mi++) {
            int rbase = m0 + wm * 32 + mi * 16 + gq;
#pragma unroll
            for (int rr = 0; rr < 2; rr++) {
                int r = rbase + rr * 8;
                int bg = r >> 10, s = r & 1023;
                size_t off = ((size_t)(bg * Hn + h) * Sn + s) * DKn + d;
                float v0 = acc[mi][ni][rr * 2 + 0] + b0v;
                float v1 = acc[mi][ni][rr * 2 + 1] + b1v;
                *(__nv_bfloat162*)&O[off] = __floats2bfloat162_rn(v0, v1);
            }
        }
    }
}

// ---------------------------------------------------------------------------
// Attention v4: single pass, 16 q-rows per CTA -> 2 CTAs/SM for write/compute
// overlap. MMA scores -> exp into full-row smem e-tile + rowsums -> invert ->
// coalesced normalized writes + column-sum atomics.
static constexpr int QR   = 16;    // q rows per CTA
static constexpr int KSTR = 72;    // bf16 row stride of k/q tiles
static constexpr int ESTR = 1032;  // fp32 row stride of e tile (1032%32==8: conflict-free)
static constexpr int SM_QS   = 0;                          // 16*72*2   = 2304
static constexpr int SM_KS   = SM_QS + QR * KSTR * 2;      // 2*128*72*2= 36864
static constexpr int SM_ES   = SM_KS + 2 * 128 * KSTR * 2; // 16*1032*4 = 66048
static constexpr int SM_RSUM = SM_ES + QR * ESTR * 4;      // 16*4
static constexpr int ATTN_SMEM = SM_RSUM + QR * 4;         // 105280 B

__global__ __launch_bounds__(256, 2) void attn_kernel(float* __restrict__ out, int p_base, int write_p)
{
    extern __shared__ char smbuf[];
    __nv_bfloat16* qs   = (__nv_bfloat16*)(smbuf + SM_QS);
    __nv_bfloat16* ksm  = (__nv_bfloat16*)(smbuf + SM_KS);
    float*         es   = (float*)(smbuf + SM_ES);
    float*         rsum = (float*)(smbuf + SM_RSUM);

    const int qt = blockIdx.x, bgh = blockIdx.y;
    const int tid = threadIdx.x;
    const int w = tid >> 5, lane = tid & 31;
    const int gq = lane >> 2, tq = lane & 3;
    // 8 warps, each owns a 16-col slice of the 128-col chunk (m=16 whole tile)

    const __nv_bfloat16* qbase = g_q + (size_t)bgh * (Sn * DKn) + (size_t)qt * QR * DKn;
    const __nv_bfloat16* kbase = g_k + (size_t)bgh * (Sn * DKn);

    // q tile (16x64 bf16) + rsum init
    if (tid < 128) {
        int r = tid >> 3, part = tid & 7;
        *(uint4*)&qs[r * KSTR + part * 8] = *(const uint4*)&qbase[r * DKn + part * 8];
    }
    if (tid < QR) rsum[tid] = 0.f;

    const float SCL = 1.0f / 1200.0f;  // 1/(sqrt(64)*150)
    const int ldr = tid >> 3, ldp = (tid & 7) * 8;   // k-chunk loader coords

    uint4 pre[4];
#pragma unroll
    for (int j = 0; j < 4; j++)
        pre[j] = *(const uint4*)&kbase[(size_t)(ldr + 32 * j) * DKn + ldp];

    float rs0 = 0.f, rs1 = 0.f;
    for (int c = 0; c < 8; c++) {
        __nv_bfloat16* kbuf = ksm + (c & 1) * 128 * KSTR;
#pragma unroll
        for (int j = 0; j < 4; j++)
            *(uint4*)&kbuf[(ldr + 32 * j) * KSTR + ldp] = pre[j];
        __syncthreads();
        if (c < 7) {
#pragma unroll
            for (int j = 0; j < 4; j++)
                pre[j] = *(const uint4*)&kbase[(size_t)((c + 1) * 128 + ldr + 32 * j) * DKn + ldp];
        }

        float acc[2][4];
#pragma unroll
        for (int ni = 0; ni < 2; ni++)
#pragma unroll
            for (int x = 0; x < 4; x++) acc[ni][x] = 0.f;

#pragma unroll
        for (int ks = 0; ks < 64; ks += 16) {
            uint32_t af[4];
            af[0] = *(const uint32_t*)&qs[gq * KSTR + ks + 2 * tq];
            af[1] = *(const uint32_t*)&qs[(gq + 8) * KSTR + ks + 2 * tq];
            af[2] = *(const uint32_t*)&qs[gq * KSTR + ks + 2 * tq + 8];
            af[3] = *(const uint32_t*)&qs[(gq + 8) * KSTR + ks + 2 * tq + 8];
#pragma unroll
            for (int ni = 0; ni < 2; ni++) {
                int br = w * 16 + ni * 8 + gq;
                uint32_t bf[2];
                bf[0] = *(const uint32_t*)&kbuf[br * KSTR + ks + 2 * tq];
                bf[1] = *(const uint32_t*)&kbuf[br * KSTR + ks + 2 * tq + 8];
                mma16816(acc[ni], af, bf);
            }
        }

        // exp -> e-tile (full row) + rowsum partials
#pragma unroll
        for (int ni = 0; ni < 2; ni++) {
            int cc = c * 128 + w * 16 + ni * 8 + 2 * tq;
            float e00 = __expf(acc[ni][0] * SCL);
            float e01 = __expf(acc[ni][1] * SCL);
            float e10 = __expf(acc[ni][2] * SCL);
            float e11 = __expf(acc[ni][3] * SCL);
            *(float2*)&es[gq * ESTR + cc]       = make_float2(e00, e01);
            *(float2*)&es[(gq + 8) * ESTR + cc] = make_float2(e10, e11);
            rs0 += e00 + e01;
            rs1 += e10 + e11;
        }
        // double-buffered: no trailing sync needed
    }

    rs0 += __shfl_xor_sync(0xffffffffu, rs0, 1);
    rs0 += __shfl_xor_sync(0xffffffffu, rs0, 2);
    rs1 += __shfl_xor_sync(0xffffffffu, rs1, 1);
    rs1 += __shfl_xor_sync(0xffffffffu, rs1, 2);
    if (tq == 0) {
        atomicAdd(&rsum[gq], rs0);
        atomicAdd(&rsum[gq + 8], rs1);
    }
    __syncthreads();
    if (tid < QR) rsum[tid] = 1.0f / rsum[tid];
    __syncthreads();

    // normalize + write p + column sums (thread owns cols tid*4..+3)
    float cs0 = 0.f, cs1 = 0.f, cs2 = 0.f, cs3 = 0.f;
    float* pout = out + p_base + (size_t)bgh * ((size_t)Sn * Sn) + (size_t)(qt * QR) * Sn;
#pragma unroll 4
    for (int r = 0; r < QR; r++) {
        float inv = rsum[r];
        float4 v = *(const float4*)&es[r * ESTR + tid * 4];
        v.x *= inv; v.y *= inv; v.z *= inv; v.w *= inv;
        cs0 += v.x; cs1 += v.y; cs2 += v.z; cs3 += v.w;
        if (write_p) *(float4*)&pout[(size_t)r * Sn + tid * 4] = v;
    }
    atomicAdd(&g_wbar[bgh * Sn + tid * 4 + 0], cs0);
    atomicAdd(&g_wbar[bgh * Sn + tid * 4 + 1], cs1);
    atomicAdd(&g_wbar[bgh * Sn + tid * 4 + 2], cs2);
    atomicAdd(&g_wbar[bgh * Sn + tid * 4 + 3], cs3);
}

// ---------------------------------------------------------------------------
// t = (wbar/1024) @ Xv, parallelized over (bg, 16 S-chunks of 64).
__global__ __launch_bounds__(256) void t_kernel(const float* __restrict__ value)
{
    __shared__ float wb[8][64];
    const int bg = blockIdx.x, kc = blockIdx.y;
    const int tid = threadIdx.x;

    for (int j = tid; j < 512; j += 256) {
        int h = j >> 6, k = j & 63;
        wb[h][k] = g_wbar[(bg * 8 + h) * Sn + kc * 64 + k] * (1.0f / 1024.0f);
    }
    __syncthreads();

    float a[8][2];
#pragma unroll
    for (int h = 0; h < 8; h++) { a[h][0] = 0.f; a[h][1] = 0.f; }

    const float* __restrict__ xv = value + (size_t)bg * (Sn * DMn) + (size_t)(kc * 64) * DMn;
#pragma unroll 4
    for (int k = 0; k < 64; k++) {
        float x0 = xv[k * DMn + tid];
        float x1 = xv[k * DMn + tid + 256];
#pragma unroll
        for (int h = 0; h < 8; h++) {
            a[h][0] += wb[h][k] * x0;
            a[h][1] += wb[h][k] * x1;
        }
    }
#pragma unroll
    for (int h = 0; h < 8; h++) {
        atomicAdd(&g_t[(bg * 8 + h) * DMn + tid],       a[h][0]);
        atomicAdd(&g_t[(bg * 8 + h) * DMn + tid + 256], a[h][1]);
    }
}

// ---------------------------------------------------------------------------
// finalize2: out_hd = t_h . Wv[h*64+d] + bv ; f[d*8+h] = out_hd ;
// y = f @ Wo^T + bo.  One CTA per (b,g), 512 threads, row-contiguous W loads.
__global__ __launch_bounds__(512) void finalize2_kernel(
    const float* __restrict__ Wv, const float* __restrict__ bv,
    const float* __restrict__ Wo, const float* __restrict__ bo,
    float* __restrict__ out, int write_y)
{
    __shared__ float ts[8 * 512];
    __shared__ float fs[512];
    const int bg = blockIdx.x, tid = threadIdx.x;

#pragma unroll
    for (int j = 0; j < 8; j++) ts[j * 512 + tid] = g_t[bg * 4096 + j * 512 + tid];
    __syncthreads();

    {
        int h = tid >> 6, d = tid & 63;
        const float4* __restrict__ wr = (const float4*)(Wv + (size_t)tid * DMn);
        const float* th = ts + h * 512;
        float o0 = 0, o1 = 0, o2 = 0, o3 = 0;
#pragma unroll 8
        for (int c = 0; c < 128; c++) {
            float4 w4 = wr[c];
            o0 += th[4 * c + 0] * w4.x;
            o1 += th[4 * c + 1] * w4.y;
            o2 += th[4 * c + 2] * w4.z;
            o3 += th[4 * c + 3] * w4.w;
        }
        fs[d * 8 + h] = bv[tid] + ((o0 + o1) + (o2 + o3));
    }
    __syncthreads();

    if (write_y) {
        const float4* __restrict__ wr = (const float4*)(Wo + (size_t)tid * DMn);
        float o0 = 0, o1 = 0, o2 = 0, o3 = 0;
#pragma unroll 8
        for (int c = 0; c < 128; c++) {
            float4 w4 = wr[c];
            o0 += fs[4 * c + 0] * w4.x;
            o1 += fs[4 * c + 1] * w4.y;
            o2 += fs[4 * c + 2] * w4.z;
            o3 += fs[4 * c + 3] * w4.w;
        }
        out[bg * DMn + tid] = bo[tid] + ((o0 + o1) + (o2 + o3));
    }
}

// ---------------------------------------------------------------------------
extern "C" void kernel_launch(void* const* d_in, const int* in_sizes, int n_in,
                              void* d_out, int out_size)
{
    if (n_in < 11) return;
    const float* query = (const float*)d_in[0];
    const float* key   = (const float*)d_in[1];
    const float* value = (const float*)d_in[2];
    const float* Wq = (const float*)d_in[3];
    const float* bq = (const float*)d_in[4];
    const float* Wk = (const float*)d_in[5];
    const float* bk = (const float*)d_in[6];
    const float* Wv = (const float*)d_in[7];
    const float* bv = (const float*)d_in[8];
    const float* Wo = (const float*)d_in[9];
    const float* bo = (const float*)d_in[10];
    float* out = (float*)d_out;

    const int write_p = (out_size >= P_ELEMS) ? 1 : 0;
    const int p_base  = (out_size > P_ELEMS) ? Y_ELEMS : 0;
    const int write_y = (out_size == Y_ELEMS || out_size == Y_ELEMS + P_ELEMS) ? 1 : 0;

    cudaFuncSetAttribute((const void*)attn_kernel,
                         cudaFuncAttributeMaxDynamicSharedMemorySize, ATTN_SMEM);

    zero_kernel<<<288, 256>>>();
    proj_kernel<<<dim3(192, 4, 2), 256>>>(query, key, Wq, bq, Wk, bk);
    attn_kernel<<<dim3(64, 192), 256, ATTN_SMEM>>>(out, p_base, write_p);
    t_kernel<<<dim3(BG, 16), 256>>>(value);
    finalize2_kernel<<<BG, 512>>>(Wv, bv, Wo, bo, out, write_y);
}